// round 8
// baseline (speedup 1.0000x reference)
#include <cuda_runtime.h>
#include <cuda_fp16.h>
#include <cstdint>

// ---------------------------------------------------------------------------
// xLSTM cell, fused, portable sm_103 path (no "a" features):
//   pass 1: convert x,h,W,U fp32 -> fp16 scratch (static __device__ buffers)
//   pass 2: G[8192,4096] = [x|h] @ [W|U]^T via mma.m16n8k16.f16, fp32 accum,
//           gating epilogue fused.
//
// R8 vs R7: warp tile 64x32 -> 64x64 (acc 128 regs), CTA 128m x 64hc,
// 1 CTA/SM, 4-stage cp.async pipeline (48KB/stage, 192KB). Rationale: R7 ncu
// showed smem BW co-binding with tensor (L1=55.7% vs tensor=64.8%); smem
// reads per MMA scale as (m+n)/(m*n) -> bigger warp tile cuts traffic 1.45x.
// fp16's 4.0 MMA:LDSM ratio keeps 2 warps/SMSP busy (unlike tf32 R4).
// Grid 1024 = 64m x 16h.
// ---------------------------------------------------------------------------

#define NTHREADS 256
#define STAGES 4
#define A_TILE_BYTES 16384            // 128 rows x 128B (64 fp16)
#define B_TILE_BYTES 32768            // 256 rows (4g x 64hc) x 128B
#define STAGE_BYTES  (A_TILE_BYTES + B_TILE_BYTES)   // 49152
#define SMEM_TOTAL   (STAGES * STAGE_BYTES)          // 196608

#define N_X 8388608                   // 8192*1024
#define N_W 4194304                   // 4*1024*1024

__device__ __align__(16) __half g_x16[N_X];
__device__ __align__(16) __half g_h16[N_X];
__device__ __align__(16) __half g_W16[N_W];
__device__ __align__(16) __half g_U16[N_W];

#define SWZ(o) ((o) ^ (((o) >> 3) & 0x70))

static __device__ __forceinline__ uint32_t smem_u32(const void* p) {
    uint32_t a;
    asm("{ .reg .u64 t; cvta.to.shared.u64 t, %1; cvt.u32.u64 %0, t; }"
        : "=r"(a) : "l"(p));
    return a;
}

#define CP_ASYNC16(dst, src) \
    asm volatile("cp.async.cg.shared.global [%0], [%1], 16;" :: "r"(dst), "l"(src) : "memory")
#define CP_COMMIT() asm volatile("cp.async.commit_group;" ::: "memory")
#define CP_WAIT2()  asm volatile("cp.async.wait_group 2;" ::: "memory")

#define LDMATRIX_X4(r0, r1, r2, r3, addr) \
    asm volatile("ldmatrix.sync.aligned.m8n8.x4.shared.b16 {%0,%1,%2,%3}, [%4];" \
                 : "=r"(r0), "=r"(r1), "=r"(r2), "=r"(r3) : "r"(addr))

#define MMA_F16(d, a, b0, b1) \
    asm volatile("mma.sync.aligned.m16n8k16.row.col.f32.f16.f16.f32 " \
                 "{%0,%1,%2,%3}, {%4,%5,%6,%7}, {%8,%9}, {%0,%1,%2,%3};" \
                 : "+f"((d)[0]), "+f"((d)[1]), "+f"((d)[2]), "+f"((d)[3]) \
                 : "r"((a)[0]), "r"((a)[1]), "r"((a)[2]), "r"((a)[3]), \
                   "r"(b0), "r"(b1))

static __device__ __forceinline__ float sigmoidf_(float v) {
    return 1.0f / (1.0f + __expf(-v));
}
static __device__ __forceinline__ float tanhf_(float v) {
    return 1.0f - 2.0f / (__expf(2.0f * v) + 1.0f);
}

// ---------------- pass 1: fp32 -> fp16 conversion --------------------------
__global__ void __launch_bounds__(256) cvt_f32_to_f16_kernel(
    const float* __restrict__ x, const float* __restrict__ h,
    const float* __restrict__ W, const float* __restrict__ U)
{
    const long long n4x = N_X / 4, n4w = N_W / 4;
    const long long total = 2 * n4x + 2 * n4w;
    const long long stride = (long long)gridDim.x * blockDim.x;
    for (long long i = (long long)blockIdx.x * blockDim.x + threadIdx.x;
         i < total; i += stride) {
        const float* s;
        __half* d;
        long long j;
        if (i < n4x)                { s = x; d = g_x16; j = i; }
        else if (i < 2 * n4x)       { s = h; d = g_h16; j = i - n4x; }
        else if (i < 2 * n4x + n4w) { s = W; d = g_W16; j = i - 2 * n4x; }
        else                        { s = U; d = g_U16; j = i - 2 * n4x - n4w; }
        float4 v = reinterpret_cast<const float4*>(s)[j];
        __half2 lo = __floats2half2_rn(v.x, v.y);
        __half2 hi = __floats2half2_rn(v.z, v.w);
        uint2 u;
        u.x = *reinterpret_cast<uint32_t*>(&lo);
        u.y = *reinterpret_cast<uint32_t*>(&hi);
        reinterpret_cast<uint2*>(d)[j] = u;
    }
}

// Load one BK=64 chunk (A 128x64 fp16 + B [4g x 64hc] x 64 fp16) into a stage.
static __device__ __forceinline__ void load_chunk64(
    int kc, uint32_t stage_sm,
    const uint32_t* dstA, const int* srcA,
    const uint32_t* dstB, const int* srcB)
{
    const __half* ap = (kc < 16) ? g_x16 : g_h16;
    const __half* bp = (kc < 16) ? g_W16 : g_U16;
    int k0 = (kc & 15) << 6;
    uint32_t sB = stage_sm + A_TILE_BYTES;
#pragma unroll
    for (int j = 0; j < 4; j++) CP_ASYNC16(stage_sm + dstA[j], ap + srcA[j] + k0);
#pragma unroll
    for (int j = 0; j < 8; j++) CP_ASYNC16(sB + dstB[j], bp + srcB[j] + k0);
}

__global__ void __launch_bounds__(NTHREADS, 1) xlstm_f16_mma_kernel(
    const float* __restrict__ cprev,
    const float* __restrict__ bW, const float* __restrict__ bU,
    float* __restrict__ o1, float* __restrict__ o2, float* __restrict__ oc)
{
    extern __shared__ char smem[];
    const uint32_t sbase = smem_u32(smem);

    const int tid  = threadIdx.x;
    const int lane = tid & 31;
    const int warp = tid >> 5;
    const int warp_m = warp >> 2;      // 0..1 : 64 m-rows each
    const int warp_n = warp & 3;       // 0..3 : 16 h-cols each (x4 gates)

    const int bid = blockIdx.x;
    const int m0 = (bid >> 4) << 7;    // 64 m-tiles of 128
    const int h0 = (bid & 15) << 6;    // 16 h-tiles of 64

    // ---- cp.async per-thread offsets ----
    // A: 1024 slots (4/thread). B: 2048 slots (8/thread). 16B = 8 fp16 per slot.
    uint32_t dstA[4], dstB[8];
    int srcA[4], srcB[8];
#pragma unroll
    for (int j = 0; j < 8; j++) {
        int slot = tid + j * NTHREADS;
        int r = slot >> 3, cq = slot & 7;
        dstB[j] = SWZ((uint32_t)(r * 128 + cq * 16));
        int g = r >> 6, hc = r & 63;         // B rows: gate-major [4][64]
        srcB[j] = g * 1048576 + (h0 + hc) * 1024 + cq * 8;
        if (j < 4) {
            dstA[j] = dstB[j];               // same slot->offset formula
            srcA[j] = (m0 + r) * 1024 + cq * 8;
        }
    }

    // ---- ldmatrix per-thread address components ----
    const uint32_t xorv = (uint32_t)(lane & 7) << 4;
    // A (m16k16 per x4): lanes 0-15 -> rows @ k8-lo chunk, 16-31 -> k8-hi.
    uint32_t aOff[4];
#pragma unroll
    for (int mt = 0; mt < 4; mt++)
        aOff[mt] = (uint32_t)(warp_m * 64 + mt * 16 + (lane & 15)) * 128u;
    uint32_t aSel[4];
#pragma unroll
    for (int s = 0; s < 4; s++)
        aSel[s] = ((uint32_t)(s * 32) + ((uint32_t)(lane >> 4) << 4)) ^ xorv;
    // B (n8 x k32 per x4): rows = gate*64 + warp_n*16 + nh*8 + lane%8,
    // lane>>3 selects the k8 quarter within the 64B half-row.
    uint32_t bOff[4][2];
#pragma unroll
    for (int g = 0; g < 4; g++)
#pragma unroll
        for (int nh = 0; nh < 2; nh++)
            bOff[g][nh] = (uint32_t)(g * 64 + warp_n * 16 + nh * 8 + (lane & 7)) * 128u;
    uint32_t bSel[2];
#pragma unroll
    for (int kh = 0; kh < 2; kh++)
        bSel[kh] = ((uint32_t)(kh * 64) + ((uint32_t)(lane >> 3) << 4)) ^ xorv;

    float acc[4][4][2][4];   // [mt][gate][nh][frag]
#pragma unroll
    for (int mt = 0; mt < 4; mt++)
#pragma unroll
        for (int g = 0; g < 4; g++)
#pragma unroll
            for (int nh = 0; nh < 2; nh++)
#pragma unroll
                for (int r = 0; r < 4; r++) acc[mt][g][nh][r] = 0.0f;

    // ---- prologue: chunks 0,1,2 into stages 0,1,2 ----
#pragma unroll
    for (int p = 0; p < STAGES - 1; p++) {
        load_chunk64(p, sbase + (uint32_t)p * STAGE_BYTES, dstA, srcA, dstB, srcB);
        CP_COMMIT();
    }

    // ---- mainloop: 32 BK=64 chunks, 4 stages ----
#pragma unroll 1
    for (int kc = 0; kc < 32; kc++) {
        CP_WAIT2();          // chunk kc resident (kc+1, kc+2 may be in flight)
        __syncthreads();     // data visible; overwritten stage drained

        if (kc + 3 < 32)
            load_chunk64(kc + 3, sbase + (uint32_t)((kc + 3) & 3) * STAGE_BYTES,
                         dstA, srcA, dstB, srcB);
        CP_COMMIT();

        const uint32_t sA = sbase + (uint32_t)(kc & 3) * STAGE_BYTES;
        const uint32_t sB = sA + A_TILE_BYTES;

#pragma unroll
        for (int kh = 0; kh < 2; kh++) {
            uint32_t b[4][2][4];   // [gate][nh][k8 quarter of this k32 half]
#pragma unroll
            for (int g = 0; g < 4; g++)
#pragma unroll
                for (int nh = 0; nh < 2; nh++)
                    LDMATRIX_X4(b[g][nh][0], b[g][nh][1], b[g][nh][2], b[g][nh][3],
                                sB + bOff[g][nh] + bSel[kh]);
#pragma unroll
            for (int t = 0; t < 2; t++) {     // two k16 steps per half
                const uint32_t aCh = aSel[kh * 2 + t];
                const int bs = t << 1;        // 0 or 2
#pragma unroll
                for (int mt = 0; mt < 4; mt++) {
                    uint32_t a[4];
                    LDMATRIX_X4(a[0], a[1], a[2], a[3], sA + aOff[mt] + aCh);
#pragma unroll
                    for (int g = 0; g < 4; g++)
#pragma unroll
                        for (int nh = 0; nh < 2; nh++)
                            MMA_F16(acc[mt][g][nh], a, b[g][nh][bs], b[g][nh][bs + 1]);
                }
            }
        }
    }

    // ---- epilogue: thread-local (all 4 gates of each (m,h) in this thread) ----
    // C frag: c0=(row l/4, col 2(l%4)); c1=+1col; c2=+8row; c3=+8row+1col
    const int hc0 = h0 + warp_n * 16 + 2 * (lane & 3);

    float bsum[4][2][2];
#pragma unroll
    for (int g = 0; g < 4; g++)
#pragma unroll
        for (int nh = 0; nh < 2; nh++)
#pragma unroll
            for (int e = 0; e < 2; e++)
                bsum[g][nh][e] = bW[g * 1024 + hc0 + nh * 8 + e]
                               + bU[g * 1024 + hc0 + nh * 8 + e];

#pragma unroll
    for (int mt = 0; mt < 4; mt++) {
#pragma unroll
        for (int rh = 0; rh < 2; rh++) {
            int m = m0 + warp_m * 64 + mt * 16 + (lane >> 2) + rh * 8;
            size_t rowb = (size_t)m * 1024;
#pragma unroll
            for (int nh = 0; nh < 2; nh++) {
                size_t base = rowb + hc0 + nh * 8;
                float2 cold = *reinterpret_cast<const float2*>(cprev + base);

                float hn[2], cn[2];
#pragma unroll
                for (int e = 0; e < 2; e++) {
                    int rr = rh * 2 + e;
                    float gi = acc[mt][0][nh][rr] + bsum[0][nh][e];
                    float gf = acc[mt][1][nh][rr] + bsum[1][nh][e];
                    float go = acc[mt][2][nh][rr] + bsum[2][nh][e];
                    float gc = acc[mt][3][nh][rr] + bsum[3][nh][e];
                    float iv = sigmoidf_(gi);
                    float fv = sigmoidf_(gf);
                    float ov = sigmoidf_(go);
                    float ch = tanhf_(gc);
                    float cold_e = (e == 0) ? cold.x : cold.y;
                    float cv = fv * cold_e + iv * ch;
                    cn[e] = cv;
                    hn[e] = ov * tanhf_(cv);
                }

                float2 hv = make_float2(hn[0], hn[1]);
                *reinterpret_cast<float2*>(o1 + base) = hv;
                if (o2) *reinterpret_cast<float2*>(o2 + base) = hv;
                if (oc) *reinterpret_cast<float2*>(oc + base) = make_float2(cn[0], cn[1]);
            }
        }
    }
}

extern "C" void kernel_launch(void* const* d_in, const int* in_sizes, int n_in,
                              void* d_out, int out_size) {
    const float* x  = (const float*)d_in[0];
    const float* h  = (const float*)d_in[1];
    const float* c  = (const float*)d_in[2];
    const float* W  = (const float*)d_in[3];
    const float* bW = (const float*)d_in[4];
    const float* U  = (const float*)d_in[5];
    const float* bU = (const float*)d_in[6];
    float* out = (float*)d_out;

    const long long BH = 8192LL * 1024LL;
    float* o1 = out;
    float* o2 = nullptr;
    float* oc = nullptr;
    if ((long long)out_size >= 3 * BH) {          // (h_new, h_new, c_new)
        o2 = out + BH;
        oc = out + 2 * BH;
    } else if ((long long)out_size >= 2 * BH) {   // (h_new, c_new)
        oc = out + BH;
    }

    cvt_f32_to_f16_kernel<<<4096, 256>>>(x, h, W, U);

    cudaFuncSetAttribute(xlstm_f16_mma_kernel,
                         cudaFuncAttributeMaxDynamicSharedMemorySize, SMEM_TOTAL);
    xlstm_f16_mma_kernel<<<1024, NTHREADS, SMEM_TOTAL>>>(c, bW, bU, o1, o2, oc);
}

// round 9
// speedup vs baseline: 1.1390x; 1.1390x over previous
#include <cuda_runtime.h>
#include <cuda_fp16.h>
#include <cstdint>

// ---------------------------------------------------------------------------
// xLSTM cell, fused, portable sm_103 path (no "a" features):
//   pass 1: convert x,h,W,U fp32 -> fp16 scratch (static __device__ buffers)
//   pass 2: G[8192,4096] = [x|h] @ [W|U]^T via mma.m16n8k16.f16, fp32 accum,
//           gating epilogue fused.
//
// R9 vs R7 (best, 379us): SAME per-warp kernel (warp tile 64x32, acc 64,
// 4 warps/SMSP -- R8 proved occupancy is the binding factor), but ONE
// 512-thread CTA/SM instead of two 256-thread CTAs:
//   - B tile (4g x 64hc) shared by 8 n-warps -> B loaded once per SM/chunk
//     (cp.async 8 -> 6 per thread, L2 B traffic halved)
//   - smem cap 227KB -> 4-stage pipeline (48KB/stage, 192KB)
//   - chunk top reordered: barrier -> B LDSM -> prefetch -> MMAs
// Grid 1024 = 64m x 16h. CTA tile 128m x 256n; 16 warps as 2m x 8n.
// ---------------------------------------------------------------------------

#define NTHREADS 512
#define STAGES 4
#define A_TILE_BYTES 16384            // 128 rows x 128B (64 fp16)
#define B_TILE_BYTES 32768            // 256 rows (4g x 64hc) x 128B
#define STAGE_BYTES  (A_TILE_BYTES + B_TILE_BYTES)   // 49152
#define SMEM_TOTAL   (STAGES * STAGE_BYTES)          // 196608

#define N_X 8388608                   // 8192*1024
#define N_W 4194304                   // 4*1024*1024

__device__ __align__(16) __half g_x16[N_X];
__device__ __align__(16) __half g_h16[N_X];
__device__ __align__(16) __half g_W16[N_W];
__device__ __align__(16) __half g_U16[N_W];

#define SWZ(o) ((o) ^ (((o) >> 3) & 0x70))

static __device__ __forceinline__ uint32_t smem_u32(const void* p) {
    uint32_t a;
    asm("{ .reg .u64 t; cvta.to.shared.u64 t, %1; cvt.u32.u64 %0, t; }"
        : "=r"(a) : "l"(p));
    return a;
}

#define CP_ASYNC16(dst, src) \
    asm volatile("cp.async.cg.shared.global [%0], [%1], 16;" :: "r"(dst), "l"(src) : "memory")
#define CP_COMMIT() asm volatile("cp.async.commit_group;" ::: "memory")
#define CP_WAIT2()  asm volatile("cp.async.wait_group 2;" ::: "memory")

#define LDMATRIX_X4(r0, r1, r2, r3, addr) \
    asm volatile("ldmatrix.sync.aligned.m8n8.x4.shared.b16 {%0,%1,%2,%3}, [%4];" \
                 : "=r"(r0), "=r"(r1), "=r"(r2), "=r"(r3) : "r"(addr))

#define MMA_F16(d, a, b0, b1) \
    asm volatile("mma.sync.aligned.m16n8k16.row.col.f32.f16.f16.f32 " \
                 "{%0,%1,%2,%3}, {%4,%5,%6,%7}, {%8,%9}, {%0,%1,%2,%3};" \
                 : "+f"((d)[0]), "+f"((d)[1]), "+f"((d)[2]), "+f"((d)[3]) \
                 : "r"((a)[0]), "r"((a)[1]), "r"((a)[2]), "r"((a)[3]), \
                   "r"(b0), "r"(b1))

static __device__ __forceinline__ float sigmoidf_(float v) {
    return 1.0f / (1.0f + __expf(-v));
}
static __device__ __forceinline__ float tanhf_(float v) {
    return 1.0f - 2.0f / (__expf(2.0f * v) + 1.0f);
}

// ---------------- pass 1: fp32 -> fp16 conversion --------------------------
__global__ void __launch_bounds__(256) cvt_f32_to_f16_kernel(
    const float* __restrict__ x, const float* __restrict__ h,
    const float* __restrict__ W, const float* __restrict__ U)
{
    const long long n4x = N_X / 4, n4w = N_W / 4;
    const long long total = 2 * n4x + 2 * n4w;
    const long long stride = (long long)gridDim.x * blockDim.x;
    for (long long i = (long long)blockIdx.x * blockDim.x + threadIdx.x;
         i < total; i += stride) {
        const float* s;
        __half* d;
        long long j;
        if (i < n4x)                { s = x; d = g_x16; j = i; }
        else if (i < 2 * n4x)       { s = h; d = g_h16; j = i - n4x; }
        else if (i < 2 * n4x + n4w) { s = W; d = g_W16; j = i - 2 * n4x; }
        else                        { s = U; d = g_U16; j = i - 2 * n4x - n4w; }
        float4 v = reinterpret_cast<const float4*>(s)[j];
        __half2 lo = __floats2half2_rn(v.x, v.y);
        __half2 hi = __floats2half2_rn(v.z, v.w);
        uint2 u;
        u.x = *reinterpret_cast<uint32_t*>(&lo);
        u.y = *reinterpret_cast<uint32_t*>(&hi);
        reinterpret_cast<uint2*>(d)[j] = u;
    }
}

// Load one BK=64 chunk (A 128x64 fp16 + B [4g x 64hc] x 64 fp16) into a stage.
static __device__ __forceinline__ void load_chunk64(
    int kc, uint32_t stage_sm,
    const uint32_t* dstA, const int* srcA,
    const uint32_t* dstB, const int* srcB)
{
    const __half* ap = (kc < 16) ? g_x16 : g_h16;
    const __half* bp = (kc < 16) ? g_W16 : g_U16;
    int k0 = (kc & 15) << 6;
    uint32_t sB = stage_sm + A_TILE_BYTES;
#pragma unroll
    for (int j = 0; j < 2; j++) CP_ASYNC16(stage_sm + dstA[j], ap + srcA[j] + k0);
#pragma unroll
    for (int j = 0; j < 4; j++) CP_ASYNC16(sB + dstB[j], bp + srcB[j] + k0);
}

__global__ void __launch_bounds__(NTHREADS, 1) xlstm_f16_mma_kernel(
    const float* __restrict__ cprev,
    const float* __restrict__ bW, const float* __restrict__ bU,
    float* __restrict__ o1, float* __restrict__ o2, float* __restrict__ oc)
{
    extern __shared__ char smem[];
    const uint32_t sbase = smem_u32(smem);

    const int tid  = threadIdx.x;
    const int lane = tid & 31;
    const int warp = tid >> 5;
    const int warp_m = warp >> 3;      // 0..1 : 64 m-rows each
    const int warp_n = warp & 7;       // 0..7 : 8 h-cols each (x4 gates)

    const int bid = blockIdx.x;
    const int m0 = (bid >> 4) << 7;    // 64 m-tiles of 128
    const int h0 = (bid & 15) << 6;    // 16 h-tiles of 64

    // ---- cp.async per-thread offsets ----
    // A: 1024 slots (2/thread). B: 2048 slots (4/thread). 16B = 8 fp16/slot.
    uint32_t dstA[2], dstB[4];
    int srcA[2], srcB[4];
#pragma unroll
    for (int j = 0; j < 4; j++) {
        int slot = tid + j * NTHREADS;
        int r = slot >> 3, cq = slot & 7;
        dstB[j] = SWZ((uint32_t)(r * 128 + cq * 16));
        int g = r >> 6, hc = r & 63;         // B rows: gate-major [4][64]
        srcB[j] = g * 1048576 + (h0 + hc) * 1024 + cq * 8;
        if (j < 2) {
            dstA[j] = dstB[j];               // same slot->offset formula
            srcA[j] = (m0 + r) * 1024 + cq * 8;
        }
    }

    // ---- ldmatrix per-thread address components ----
    const uint32_t xorv = (uint32_t)(lane & 7) << 4;
    // A (m16k16 per x4): lanes 0-15 -> rows @ k8-lo chunk, 16-31 -> k8-hi.
    uint32_t aOff[4];
#pragma unroll
    for (int mt = 0; mt < 4; mt++)
        aOff[mt] = (uint32_t)(warp_m * 64 + mt * 16 + (lane & 15)) * 128u;
    uint32_t aSel[4];
#pragma unroll
    for (int s = 0; s < 4; s++)
        aSel[s] = ((uint32_t)(s * 32) + ((uint32_t)(lane >> 4) << 4)) ^ xorv;
    // B (n8 x k32 per x4): rows = gate*64 + warp_n*8 + lane%8,
    // lane>>3 selects the k8 quarter within the 64B half-row.
    uint32_t bOff[4];
#pragma unroll
    for (int g = 0; g < 4; g++)
        bOff[g] = (uint32_t)(g * 64 + warp_n * 8 + (lane & 7)) * 128u;
    uint32_t bSel[2];
#pragma unroll
    for (int kh = 0; kh < 2; kh++)
        bSel[kh] = ((uint32_t)(kh * 64) + ((uint32_t)(lane >> 3) << 4)) ^ xorv;

    float acc[4][4][4];   // [mt][gate][frag]
#pragma unroll
    for (int mt = 0; mt < 4; mt++)
#pragma unroll
        for (int g = 0; g < 4; g++)
#pragma unroll
            for (int r = 0; r < 4; r++) acc[mt][g][r] = 0.0f;

    // ---- prologue: chunks 0,1,2 into stages 0,1,2 ----
#pragma unroll
    for (int p = 0; p < STAGES - 1; p++) {
        load_chunk64(p, sbase + (uint32_t)p * STAGE_BYTES, dstA, srcA, dstB, srcB);
        CP_COMMIT();
    }

    // ---- mainloop: 32 BK=64 chunks, 4 stages ----
#pragma unroll 1
    for (int kc = 0; kc < 32; kc++) {
        CP_WAIT2();          // chunk kc resident (kc+1, kc+2 may be in flight)
        __syncthreads();     // data visible; overwritten stage fully consumed

        const uint32_t sA = sbase + (uint32_t)(kc & 3) * STAGE_BYTES;
        const uint32_t sB = sA + A_TILE_BYTES;

        // restart tensor feed first: B fragments for k-half 0
        uint32_t b[4][4];   // [gate][k8 quarter of current k32 half]
#pragma unroll
        for (int g = 0; g < 4; g++)
            LDMATRIX_X4(b[g][0], b[g][1], b[g][2], b[g][3],
                        sB + bOff[g] + bSel[0]);

        // then issue next chunk's global loads (non-blocking)
        if (kc + 3 < 32)
            load_chunk64(kc + 3, sbase + (uint32_t)((kc + 3) & 3) * STAGE_BYTES,
                         dstA, srcA, dstB, srcB);
        CP_COMMIT();

#pragma unroll
        for (int kh = 0; kh < 2; kh++) {
            if (kh == 1) {
#pragma unroll
                for (int g = 0; g < 4; g++)
                    LDMATRIX_X4(b[g][0], b[g][1], b[g][2], b[g][3],
                                sB + bOff[g] + bSel[1]);
            }
#pragma unroll
            for (int t = 0; t < 2; t++) {     // two k16 steps per half
                const uint32_t aCh = aSel[kh * 2 + t];
                const int bs = t << 1;        // 0 or 2
#pragma unroll
                for (int mt = 0; mt < 4; mt++) {
                    uint32_t a[4];
                    LDMATRIX_X4(a[0], a[1], a[2], a[3], sA + aOff[mt] + aCh);
#pragma unroll
                    for (int g = 0; g < 4; g++)
                        MMA_F16(acc[mt][g], a, b[g][bs], b[g][bs + 1]);
                }
            }
        }
    }

    // ---- epilogue: thread-local (all 4 gates of each (m,h) in this thread) ----
    // C frag: c0=(row l/4, col 2(l%4)); c1=+1col; c2=+8row; c3=+8row+1col
    const int hc0 = h0 + warp_n * 8 + 2 * (lane & 3);

    float bsum[4][2];
#pragma unroll
    for (int g = 0; g < 4; g++)
#pragma unroll
        for (int e = 0; e < 2; e++)
            bsum[g][e] = bW[g * 1024 + hc0 + e] + bU[g * 1024 + hc0 + e];

#pragma unroll
    for (int mt = 0; mt < 4; mt++) {
#pragma unroll
        for (int rh = 0; rh < 2; rh++) {
            int m = m0 + warp_m * 64 + mt * 16 + (lane >> 2) + rh * 8;
            size_t base = (size_t)m * 1024 + hc0;
            float2 cold = *reinterpret_cast<const float2*>(cprev + base);

            float hn[2], cn[2];
#pragma unroll
            for (int e = 0; e < 2; e++) {
                int rr = rh * 2 + e;
                float gi = acc[mt][0][rr] + bsum[0][e];
                float gf = acc[mt][1][rr] + bsum[1][e];
                float go = acc[mt][2][rr] + bsum[2][e];
                float gc = acc[mt][3][rr] + bsum[3][e];
                float iv = sigmoidf_(gi);
                float fv = sigmoidf_(gf);
                float ov = sigmoidf_(go);
                float ch = tanhf_(gc);
                float cold_e = (e == 0) ? cold.x : cold.y;
                float cv = fv * cold_e + iv * ch;
                cn[e] = cv;
                hn[e] = ov * tanhf_(cv);
            }

            float2 hv = make_float2(hn[0], hn[1]);
            *reinterpret_cast<float2*>(o1 + base) = hv;
            if (o2) *reinterpret_cast<float2*>(o2 + base) = hv;
            if (oc) *reinterpret_cast<float2*>(oc + base) = make_float2(cn[0], cn[1]);
        }
    }
}

extern "C" void kernel_launch(void* const* d_in, const int* in_sizes, int n_in,
                              void* d_out, int out_size) {
    const float* x  = (const float*)d_in[0];
    const float* h  = (const float*)d_in[1];
    const float* c  = (const float*)d_in[2];
    const float* W  = (const float*)d_in[3];
    const float* bW = (const float*)d_in[4];
    const float* U  = (const float*)d_in[5];
    const float* bU = (const float*)d_in[6];
    float* out = (float*)d_out;

    const long long BH = 8192LL * 1024LL;
    float* o1 = out;
    float* o2 = nullptr;
    float* oc = nullptr;
    if ((long long)out_size >= 3 * BH) {          // (h_new, h_new, c_new)
        o2 = out + BH;
        oc = out + 2 * BH;
    } else if ((long long)out_size >= 2 * BH) {   // (h_new, c_new)
        oc = out + BH;
    }

    cvt_f32_to_f16_kernel<<<4096, 256>>>(x, h, W, U);

    cudaFuncSetAttribute(xlstm_f16_mma_kernel,
                         cudaFuncAttributeMaxDynamicSharedMemorySize, SMEM_TOTAL);
    xlstm_f16_mma_kernel<<<1024, NTHREADS, SMEM_TOTAL>>>(c, bW, bU, o1, o2, oc);
}

// round 10
// speedup vs baseline: 1.2695x; 1.1146x over previous
#include <cuda_runtime.h>
#include <cuda_fp16.h>
#include <cstdint>

// ---------------------------------------------------------------------------
// xLSTM cell, fused, portable sm_103 path (no "a" features):
//   pass 1: convert x,h,W,U fp32 -> fp16 scratch (static __device__ buffers)
//   pass 2: G[8192,4096] = [x|h] @ [W|U]^T via mma.m16n8k16.f16, fp32 accum,
//           gating epilogue fused.
//
// R10 = R7 (best, 379us) + two local refinements:
//   (1) k-loop unrolled by 3 -> compile-time stage offsets (kills cur/pf
//       rotation ALU; R7 ncu: alu=12%, issue=28.9%)
//   (2) chunk top: barrier -> B(kh0) LDSM -> cp.async prefetch -> MMAs
//       (tensor restarts ~8 issue slots earlier per chunk)
// Shape unchanged from R7 (R8/R9 proved both neighbors lose): two 256-thread
// CTAs/SM, CTA 128m x (4g x 32hc), warp 64x32, acc 64, 3-stage 32KB/stage,
// grid 2048 = 64m x 32h.
// ---------------------------------------------------------------------------

#define NTHREADS 256
#define STAGES 3
#define A_TILE_BYTES 16384            // 128 rows x 128B (64 fp16)
#define B_TILE_BYTES 16384            // 128 rows (4g x 32hc) x 128B
#define STAGE_BYTES  (A_TILE_BYTES + B_TILE_BYTES)   // 32768
#define SMEM_TOTAL   (STAGES * STAGE_BYTES)          // 98304

#define N_X 8388608                   // 8192*1024
#define N_W 4194304                   // 4*1024*1024

__device__ __align__(16) __half g_x16[N_X];
__device__ __align__(16) __half g_h16[N_X];
__device__ __align__(16) __half g_W16[N_W];
__device__ __align__(16) __half g_U16[N_W];

#define SWZ(o) ((o) ^ (((o) >> 3) & 0x70))

static __device__ __forceinline__ uint32_t smem_u32(const void* p) {
    uint32_t a;
    asm("{ .reg .u64 t; cvta.to.shared.u64 t, %1; cvt.u32.u64 %0, t; }"
        : "=r"(a) : "l"(p));
    return a;
}

#define CP_ASYNC16(dst, src) \
    asm volatile("cp.async.cg.shared.global [%0], [%1], 16;" :: "r"(dst), "l"(src) : "memory")
#define CP_COMMIT() asm volatile("cp.async.commit_group;" ::: "memory")
#define CP_WAIT1()  asm volatile("cp.async.wait_group 1;" ::: "memory")

#define LDMATRIX_X4(r0, r1, r2, r3, addr) \
    asm volatile("ldmatrix.sync.aligned.m8n8.x4.shared.b16 {%0,%1,%2,%3}, [%4];" \
                 : "=r"(r0), "=r"(r1), "=r"(r2), "=r"(r3) : "r"(addr))

#define MMA_F16(d, a, b0, b1) \
    asm volatile("mma.sync.aligned.m16n8k16.row.col.f32.f16.f16.f32 " \
                 "{%0,%1,%2,%3}, {%4,%5,%6,%7}, {%8,%9}, {%0,%1,%2,%3};" \
                 : "+f"((d)[0]), "+f"((d)[1]), "+f"((d)[2]), "+f"((d)[3]) \
                 : "r"((a)[0]), "r"((a)[1]), "r"((a)[2]), "r"((a)[3]), \
                   "r"(b0), "r"(b1))

static __device__ __forceinline__ float sigmoidf_(float v) {
    return 1.0f / (1.0f + __expf(-v));
}
static __device__ __forceinline__ float tanhf_(float v) {
    return 1.0f - 2.0f / (__expf(2.0f * v) + 1.0f);
}

// ---------------- pass 1: fp32 -> fp16 conversion --------------------------
__global__ void __launch_bounds__(256) cvt_f32_to_f16_kernel(
    const float* __restrict__ x, const float* __restrict__ h,
    const float* __restrict__ W, const float* __restrict__ U)
{
    const long long n4x = N_X / 4, n4w = N_W / 4;
    const long long total = 2 * n4x + 2 * n4w;
    const long long stride = (long long)gridDim.x * blockDim.x;
    for (long long i = (long long)blockIdx.x * blockDim.x + threadIdx.x;
         i < total; i += stride) {
        const float* s;
        __half* d;
        long long j;
        if (i < n4x)                { s = x; d = g_x16; j = i; }
        else if (i < 2 * n4x)       { s = h; d = g_h16; j = i - n4x; }
        else if (i < 2 * n4x + n4w) { s = W; d = g_W16; j = i - 2 * n4x; }
        else                        { s = U; d = g_U16; j = i - 2 * n4x - n4w; }
        float4 v = reinterpret_cast<const float4*>(s)[j];
        __half2 lo = __floats2half2_rn(v.x, v.y);
        __half2 hi = __floats2half2_rn(v.z, v.w);
        uint2 u;
        u.x = *reinterpret_cast<uint32_t*>(&lo);
        u.y = *reinterpret_cast<uint32_t*>(&hi);
        reinterpret_cast<uint2*>(d)[j] = u;
    }
}

// Load one BK=64 chunk (A 128x64 fp16 + B [4g x 32hc] x 64 fp16) into a stage.
static __device__ __forceinline__ void load_chunk64(
    int kc, uint32_t stage_sm,
    const uint32_t* dst, const int* srcA, const int* srcB)
{
    const __half* ap = (kc < 16) ? g_x16 : g_h16;
    const __half* bp = (kc < 16) ? g_W16 : g_U16;
    int k0 = (kc & 15) << 6;
    uint32_t sB = stage_sm + A_TILE_BYTES;
#pragma unroll
    for (int j = 0; j < 4; j++) CP_ASYNC16(stage_sm + dst[j], ap + srcA[j] + k0);
#pragma unroll
    for (int j = 0; j < 4; j++) CP_ASYNC16(sB + dst[j], bp + srcB[j] + k0);
}

// One BK=64 chunk: barrier, B(kh0) LDSM, prefetch, 64 MMAs. CUR_ is a
// compile-time stage index (chunk kc uses stage kc%3; loop steps by 3).
#define CHUNK_BODY(kc_, CUR_) do {                                           \
    CP_WAIT1();                                                              \
    __syncthreads();                                                         \
    const uint32_t sA_ = sbase + (uint32_t)((CUR_) * STAGE_BYTES);           \
    const uint32_t sB_ = sA_ + A_TILE_BYTES;                                 \
    uint32_t bfr[4][4];                                                      \
    _Pragma("unroll")                                                        \
    for (int g = 0; g < 4; g++)                                              \
        LDMATRIX_X4(bfr[g][0], bfr[g][1], bfr[g][2], bfr[g][3],              \
                    sB_ + bOff[g] + bSel[0]);                                \
    if ((kc_) + 2 < 32)                                                      \
        load_chunk64((kc_) + 2,                                              \
                     sbase + (uint32_t)((((CUR_) + 2) % 3) * STAGE_BYTES),   \
                     dst, srcA, srcB);                                       \
    CP_COMMIT();                                                             \
    _Pragma("unroll")                                                        \
    for (int kh = 0; kh < 2; kh++) {                                         \
        if (kh == 1) {                                                       \
            _Pragma("unroll")                                                \
            for (int g = 0; g < 4; g++)                                      \
                LDMATRIX_X4(bfr[g][0], bfr[g][1], bfr[g][2], bfr[g][3],      \
                            sB_ + bOff[g] + bSel[1]);                        \
        }                                                                    \
        _Pragma("unroll")                                                    \
        for (int t = 0; t < 2; t++) {                                        \
            const uint32_t aCh = aSel[kh * 2 + t];                           \
            const int bs = t << 1;                                           \
            _Pragma("unroll")                                                \
            for (int mt = 0; mt < 4; mt++) {                                 \
                uint32_t afr[4];                                             \
                LDMATRIX_X4(afr[0], afr[1], afr[2], afr[3],                  \
                            sA_ + aOff[mt] + aCh);                           \
                _Pragma("unroll")                                            \
                for (int g = 0; g < 4; g++)                                  \
                    MMA_F16(acc[mt][g], afr, bfr[g][bs], bfr[g][bs + 1]);    \
            }                                                                \
        }                                                                    \
    }                                                                        \
} while (0)

__global__ void __launch_bounds__(NTHREADS, 2) xlstm_f16_mma_kernel(
    const float* __restrict__ cprev,
    const float* __restrict__ bW, const float* __restrict__ bU,
    float* __restrict__ o1, float* __restrict__ o2, float* __restrict__ oc)
{
    extern __shared__ char smem[];
    const uint32_t sbase = smem_u32(smem);

    const int tid  = threadIdx.x;
    const int lane = tid & 31;
    const int warp = tid >> 5;
    const int warp_m = warp >> 2;      // 0..1 : 64 m-rows each
    const int warp_n = warp & 3;       // 0..3 : 8 h-cols each (x4 gates)

    const int bid = blockIdx.x;
    const int m0 = (bid >> 5) << 7;    // 64 m-tiles of 128
    const int h0 = (bid & 31) << 5;    // 32 h-tiles of 32

    // ---- cp.async per-thread offsets (slot j: row r = slot/8, 16B chunk cq) ----
    // 16B = 8 fp16; a full 128-row tile = 1024 slots = 4 per thread.
    uint32_t dst[4];
    int srcA[4], srcB[4];
#pragma unroll
    for (int j = 0; j < 4; j++) {
        int slot = tid + j * NTHREADS;       // 0..1023
        int r = slot >> 3, cq = slot & 7;
        dst[j] = SWZ((uint32_t)(r * 128 + cq * 16));
        srcA[j] = (m0 + r) * 1024 + cq * 8;
        int g = r >> 5, hc = r & 31;         // B rows: gate-major [4][32]
        srcB[j] = g * 1048576 + (h0 + hc) * 1024 + cq * 8;
    }

    // ---- ldmatrix per-thread address components ----
    const uint32_t xorv = (uint32_t)(lane & 7) << 4;
    // A (m16k16 per x4): lanes 0-15 -> rows @ k8-lo chunk, 16-31 -> k8-hi.
    uint32_t aOff[4];
#pragma unroll
    for (int mt = 0; mt < 4; mt++)
        aOff[mt] = (uint32_t)(warp_m * 64 + mt * 16 + (lane & 15)) * 128u;
    uint32_t aSel[4];
#pragma unroll
    for (int s = 0; s < 4; s++)
        aSel[s] = ((uint32_t)(s * 32) + ((uint32_t)(lane >> 4) << 4)) ^ xorv;
    // B (n8 x k32 per x4): rows = gate*32 + warp_n*8 + lane%8,
    // lane>>3 selects the k8 quarter within the 64B half-row.
    uint32_t bOff[4];
#pragma unroll
    for (int g = 0; g < 4; g++)
        bOff[g] = (uint32_t)(g * 32 + warp_n * 8 + (lane & 7)) * 128u;
    uint32_t bSel[2];
#pragma unroll
    for (int kh = 0; kh < 2; kh++)
        bSel[kh] = ((uint32_t)(kh * 64) + ((uint32_t)(lane >> 3) << 4)) ^ xorv;

    float acc[4][4][4];   // [mt][gate][frag]
#pragma unroll
    for (int mt = 0; mt < 4; mt++)
#pragma unroll
        for (int g = 0; g < 4; g++)
#pragma unroll
            for (int r = 0; r < 4; r++) acc[mt][g][r] = 0.0f;

    // ---- prologue: chunks 0,1 into stages 0,1 ----
    load_chunk64(0, sbase, dst, srcA, srcB);
    CP_COMMIT();
    load_chunk64(1, sbase + STAGE_BYTES, dst, srcA, srcB);
    CP_COMMIT();

    // ---- mainloop: 32 BK=64 chunks, stage = chunk % 3 (compile-time) ----
#pragma unroll 1
    for (int kc = 0; kc < 32; kc += 3) {
        CHUNK_BODY(kc, 0);
        CHUNK_BODY(kc + 1, 1);
        if (kc + 2 < 32) CHUNK_BODY(kc + 2, 2);
    }

    // ---- epilogue: thread-local (all 4 gates of each (m,h) in this thread) ----
    // C frag: c0=(row l/4, col 2(l%4)); c1=+1col; c2=+8row; c3=+8row+1col
    const int hc0 = h0 + warp_n * 8 + 2 * (lane & 3);

    float bsum[4][2];
#pragma unroll
    for (int g = 0; g < 4; g++)
#pragma unroll
        for (int e = 0; e < 2; e++)
            bsum[g][e] = bW[g * 1024 + hc0 + e] + bU[g * 1024 + hc0 + e];

#pragma unroll
    for (int mt = 0; mt < 4; mt++) {
#pragma unroll
        for (int rh = 0; rh < 2; rh++) {
            int m = m0 + warp_m * 64 + mt * 16 + (lane >> 2) + rh * 8;
            size_t base = (size_t)m * 1024 + hc0;
            float2 cold = *reinterpret_cast<const float2*>(cprev + base);

            float hn[2], cn[2];
#pragma unroll
            for (int e = 0; e < 2; e++) {
                int rr = rh * 2 + e;
                float gi = acc[mt][0][rr] + bsum[0][e];
                float gf = acc[mt][1][rr] + bsum[1][e];
                float go = acc[mt][2][rr] + bsum[2][e];
                float gc = acc[mt][3][rr] + bsum[3][e];
                float iv = sigmoidf_(gi);
                float fv = sigmoidf_(gf);
                float ov = sigmoidf_(go);
                float ch = tanhf_(gc);
                float cold_e = (e == 0) ? cold.x : cold.y;
                float cv = fv * cold_e + iv * ch;
                cn[e] = cv;
                hn[e] = ov * tanhf_(cv);
            }

            float2 hv = make_float2(hn[0], hn[1]);
            *reinterpret_cast<float2*>(o1 + base) = hv;
            if (o2) *reinterpret_cast<float2*>(o2 + base) = hv;
            if (oc) *reinterpret_cast<float2*>(oc + base) = make_float2(cn[0], cn[1]);
        }
    }
}

extern "C" void kernel_launch(void* const* d_in, const int* in_sizes, int n_in,
                              void* d_out, int out_size) {
    const float* x  = (const float*)d_in[0];
    const float* h  = (const float*)d_in[1];
    const float* c  = (const float*)d_in[2];
    const float* W  = (const float*)d_in[3];
    const float* bW = (const float*)d_in[4];
    const float* U  = (const float*)d_in[5];
    const float* bU = (const float*)d_in[6];
    float* out = (float*)d_out;

    const long long BH = 8192LL * 1024LL;
    float* o1 = out;
    float* o2 = nullptr;
    float* oc = nullptr;
    if ((long long)out_size >= 3 * BH) {          // (h_new, h_new, c_new)
        o2 = out + BH;
        oc = out + 2 * BH;
    } else if ((long long)out_size >= 2 * BH) {   // (h_new, c_new)
        oc = out + BH;
    }

    cvt_f32_to_f16_kernel<<<4096, 256>>>(x, h, W, U);

    cudaFuncSetAttribute(xlstm_f16_mma_kernel,
                         cudaFuncAttributeMaxDynamicSharedMemorySize, SMEM_TOTAL);
    xlstm_f16_mma_kernel<<<2048, NTHREADS, SMEM_TOTAL>>>(c, bW, bU, o1, o2, oc);
}

// round 11
// speedup vs baseline: 1.2962x; 1.0211x over previous
#include <cuda_runtime.h>
#include <cuda_fp16.h>
#include <cstdint>

// ---------------------------------------------------------------------------
// xLSTM cell, fused, portable sm_103 path (no "a" features):
//   pass 1: convert x,h,W,U fp32 -> fp16 scratch (static __device__ buffers)
//   pass 2: G[8192,4096] = [x|h] @ [W|U]^T via mma.m16n8k16.f16, fp32 accum,
//           gating epilogue fused.
//
// R11 = R10 (best, 370.9us) + one change: per k16 step, ALL 4 A-LDSM are
// issued before the step's 16 MMAs (was interleaved LDSM;4xMMA per mt).
// Lengthens LDSM->consumer distance ~1 -> ~4 slots and makes each 16-MMA
// run contiguous on the tensor pipe. (R10 ncu: tensor=65.9%, distributed
// within-chunk latency is the residual -- barriers only ~2%.)
// Shape unchanged: two 256-thread CTAs/SM, CTA 128m x (4g x 32hc), warp
// 64x32, acc 64, 3-stage 32KB/stage, grid 2048 = 64m x 32h.
// ---------------------------------------------------------------------------

#define NTHREADS 256
#define STAGES 3
#define A_TILE_BYTES 16384            // 128 rows x 128B (64 fp16)
#define B_TILE_BYTES 16384            // 128 rows (4g x 32hc) x 128B
#define STAGE_BYTES  (A_TILE_BYTES + B_TILE_BYTES)   // 32768
#define SMEM_TOTAL   (STAGES * STAGE_BYTES)          // 98304

#define N_X 8388608                   // 8192*1024
#define N_W 4194304                   // 4*1024*1024

__device__ __align__(16) __half g_x16[N_X];
__device__ __align__(16) __half g_h16[N_X];
__device__ __align__(16) __half g_W16[N_W];
__device__ __align__(16) __half g_U16[N_W];

#define SWZ(o) ((o) ^ (((o) >> 3) & 0x70))

static __device__ __forceinline__ uint32_t smem_u32(const void* p) {
    uint32_t a;
    asm("{ .reg .u64 t; cvta.to.shared.u64 t, %1; cvt.u32.u64 %0, t; }"
        : "=r"(a) : "l"(p));
    return a;
}

#define CP_ASYNC16(dst, src) \
    asm volatile("cp.async.cg.shared.global [%0], [%1], 16;" :: "r"(dst), "l"(src) : "memory")
#define CP_COMMIT() asm volatile("cp.async.commit_group;" ::: "memory")
#define CP_WAIT1()  asm volatile("cp.async.wait_group 1;" ::: "memory")

#define LDMATRIX_X4(r0, r1, r2, r3, addr) \
    asm volatile("ldmatrix.sync.aligned.m8n8.x4.shared.b16 {%0,%1,%2,%3}, [%4];" \
                 : "=r"(r0), "=r"(r1), "=r"(r2), "=r"(r3) : "r"(addr))

#define MMA_F16(d, a, b0, b1) \
    asm volatile("mma.sync.aligned.m16n8k16.row.col.f32.f16.f16.f32 " \
                 "{%0,%1,%2,%3}, {%4,%5,%6,%7}, {%8,%9}, {%0,%1,%2,%3};" \
                 : "+f"((d)[0]), "+f"((d)[1]), "+f"((d)[2]), "+f"((d)[3]) \
                 : "r"((a)[0]), "r"((a)[1]), "r"((a)[2]), "r"((a)[3]), \
                   "r"(b0), "r"(b1))

static __device__ __forceinline__ float sigmoidf_(float v) {
    return 1.0f / (1.0f + __expf(-v));
}
static __device__ __forceinline__ float tanhf_(float v) {
    return 1.0f - 2.0f / (__expf(2.0f * v) + 1.0f);
}

// ---------------- pass 1: fp32 -> fp16 conversion --------------------------
__global__ void __launch_bounds__(256) cvt_f32_to_f16_kernel(
    const float* __restrict__ x, const float* __restrict__ h,
    const float* __restrict__ W, const float* __restrict__ U)
{
    const long long n4x = N_X / 4, n4w = N_W / 4;
    const long long total = 2 * n4x + 2 * n4w;
    const long long stride = (long long)gridDim.x * blockDim.x;
    for (long long i = (long long)blockIdx.x * blockDim.x + threadIdx.x;
         i < total; i += stride) {
        const float* s;
        __half* d;
        long long j;
        if (i < n4x)                { s = x; d = g_x16; j = i; }
        else if (i < 2 * n4x)       { s = h; d = g_h16; j = i - n4x; }
        else if (i < 2 * n4x + n4w) { s = W; d = g_W16; j = i - 2 * n4x; }
        else                        { s = U; d = g_U16; j = i - 2 * n4x - n4w; }
        float4 v = reinterpret_cast<const float4*>(s)[j];
        __half2 lo = __floats2half2_rn(v.x, v.y);
        __half2 hi = __floats2half2_rn(v.z, v.w);
        uint2 u;
        u.x = *reinterpret_cast<uint32_t*>(&lo);
        u.y = *reinterpret_cast<uint32_t*>(&hi);
        reinterpret_cast<uint2*>(d)[j] = u;
    }
}

// Load one BK=64 chunk (A 128x64 fp16 + B [4g x 32hc] x 64 fp16) into a stage.
static __device__ __forceinline__ void load_chunk64(
    int kc, uint32_t stage_sm,
    const uint32_t* dst, const int* srcA, const int* srcB)
{
    const __half* ap = (kc < 16) ? g_x16 : g_h16;
    const __half* bp = (kc < 16) ? g_W16 : g_U16;
    int k0 = (kc & 15) << 6;
    uint32_t sB = stage_sm + A_TILE_BYTES;
#pragma unroll
    for (int j = 0; j < 4; j++) CP_ASYNC16(stage_sm + dst[j], ap + srcA[j] + k0);
#pragma unroll
    for (int j = 0; j < 4; j++) CP_ASYNC16(sB + dst[j], bp + srcB[j] + k0);
}

// One BK=64 chunk: barrier, B(kh0) LDSM, prefetch, then per k16 step:
// 4 A-LDSM grouped first, then 16 contiguous MMAs. CUR_ is a compile-time
// stage index (chunk kc uses stage kc%3; loop steps by 3).
#define CHUNK_BODY(kc_, CUR_) do {                                           \
    CP_WAIT1();                                                              \
    __syncthreads();                                                         \
    const uint32_t sA_ = sbase + (uint32_t)((CUR_) * STAGE_BYTES);           \
    const uint32_t sB_ = sA_ + A_TILE_BYTES;                                 \
    uint32_t bfr[4][4];                                                      \
    _Pragma("unroll")                                                        \
    for (int g = 0; g < 4; g++)                                              \
        LDMATRIX_X4(bfr[g][0], bfr[g][1], bfr[g][2], bfr[g][3],              \
                    sB_ + bOff[g] + bSel[0]);                                \
    if ((kc_) + 2 < 32)                                                      \
        load_chunk64((kc_) + 2,                                              \
                     sbase + (uint32_t)((((CUR_) + 2) % 3) * STAGE_BYTES),   \
                     dst, srcA, srcB);                                       \
    CP_COMMIT();                                                             \
    _Pragma("unroll")                                                        \
    for (int kh = 0; kh < 2; kh++) {                                         \
        if (kh == 1) {                                                       \
            _Pragma("unroll")                                                \
            for (int g = 0; g < 4; g++)                                      \
                LDMATRIX_X4(bfr[g][0], bfr[g][1], bfr[g][2], bfr[g][3],      \
                            sB_ + bOff[g] + bSel[1]);                        \
        }                                                                    \
        _Pragma("unroll")                                                    \
        for (int t = 0; t < 2; t++) {                                        \
            const uint32_t aCh = aSel[kh * 2 + t];                           \
            const int bs = t << 1;                                           \
            uint32_t afr[4][4];                                              \
            _Pragma("unroll")                                                \
            for (int mt = 0; mt < 4; mt++)                                   \
                LDMATRIX_X4(afr[mt][0], afr[mt][1], afr[mt][2], afr[mt][3],  \
                            sA_ + aOff[mt] + aCh);                           \
            _Pragma("unroll")                                                \
            for (int mt = 0; mt < 4; mt++)                                   \
                _Pragma("unroll")                                            \
                for (int g = 0; g < 4; g++)                                  \
                    MMA_F16(acc[mt][g], afr[mt], bfr[g][bs], bfr[g][bs + 1]);\
        }                                                                    \
    }                                                                        \
} while (0)

__global__ void __launch_bounds__(NTHREADS, 2) xlstm_f16_mma_kernel(
    const float* __restrict__ cprev,
    const float* __restrict__ bW, const float* __restrict__ bU,
    float* __restrict__ o1, float* __restrict__ o2, float* __restrict__ oc)
{
    extern __shared__ char smem[];
    const uint32_t sbase = smem_u32(smem);

    const int tid  = threadIdx.x;
    const int lane = tid & 31;
    const int warp = tid >> 5;
    const int warp_m = warp >> 2;      // 0..1 : 64 m-rows each
    const int warp_n = warp & 3;       // 0..3 : 8 h-cols each (x4 gates)

    const int bid = blockIdx.x;
    const int m0 = (bid >> 5) << 7;    // 64 m-tiles of 128
    const int h0 = (bid & 31) << 5;    // 32 h-tiles of 32

    // ---- cp.async per-thread offsets (slot j: row r = slot/8, 16B chunk cq) ----
    // 16B = 8 fp16; a full 128-row tile = 1024 slots = 4 per thread.
    uint32_t dst[4];
    int srcA[4], srcB[4];
#pragma unroll
    for (int j = 0; j < 4; j++) {
        int slot = tid + j * NTHREADS;       // 0..1023
        int r = slot >> 3, cq = slot & 7;
        dst[j] = SWZ((uint32_t)(r * 128 + cq * 16));
        srcA[j] = (m0 + r) * 1024 + cq * 8;
        int g = r >> 5, hc = r & 31;         // B rows: gate-major [4][32]
        srcB[j] = g * 1048576 + (h0 + hc) * 1024 + cq * 8;
    }

    // ---- ldmatrix per-thread address components ----
    const uint32_t xorv = (uint32_t)(lane & 7) << 4;
    // A (m16k16 per x4): lanes 0-15 -> rows @ k8-lo chunk, 16-31 -> k8-hi.
    uint32_t aOff[4];
#pragma unroll
    for (int mt = 0; mt < 4; mt++)
        aOff[mt] = (uint32_t)(warp_m * 64 + mt * 16 + (lane & 15)) * 128u;
    uint32_t aSel[4];
#pragma unroll
    for (int s = 0; s < 4; s++)
        aSel[s] = ((uint32_t)(s * 32) + ((uint32_t)(lane >> 4) << 4)) ^ xorv;
    // B (n8 x k32 per x4): rows = gate*32 + warp_n*8 + lane%8,
    // lane>>3 selects the k8 quarter within the 64B half-row.
    uint32_t bOff[4];
#pragma unroll
    for (int g = 0; g < 4; g++)
        bOff[g] = (uint32_t)(g * 32 + warp_n * 8 + (lane & 7)) * 128u;
    uint32_t bSel[2];
#pragma unroll
    for (int kh = 0; kh < 2; kh++)
        bSel[kh] = ((uint32_t)(kh * 64) + ((uint32_t)(lane >> 3) << 4)) ^ xorv;

    float acc[4][4][4];   // [mt][gate][frag]
#pragma unroll
    for (int mt = 0; mt < 4; mt++)
#pragma unroll
        for (int g = 0; g < 4; g++)
#pragma unroll
            for (int r = 0; r < 4; r++) acc[mt][g][r] = 0.0f;

    // ---- prologue: chunks 0,1 into stages 0,1 ----
    load_chunk64(0, sbase, dst, srcA, srcB);
    CP_COMMIT();
    load_chunk64(1, sbase + STAGE_BYTES, dst, srcA, srcB);
    CP_COMMIT();

    // ---- mainloop: 32 BK=64 chunks, stage = chunk % 3 (compile-time) ----
#pragma unroll 1
    for (int kc = 0; kc < 32; kc += 3) {
        CHUNK_BODY(kc, 0);
        CHUNK_BODY(kc + 1, 1);
        if (kc + 2 < 32) CHUNK_BODY(kc + 2, 2);
    }

    // ---- epilogue: thread-local (all 4 gates of each (m,h) in this thread) ----
    // C frag: c0=(row l/4, col 2(l%4)); c1=+1col; c2=+8row; c3=+8row+1col
    const int hc0 = h0 + warp_n * 8 + 2 * (lane & 3);

    float bsum[4][2];
#pragma unroll
    for (int g = 0; g < 4; g++)
#pragma unroll
        for (int e = 0; e < 2; e++)
            bsum[g][e] = bW[g * 1024 + hc0 + e] + bU[g * 1024 + hc0 + e];

#pragma unroll
    for (int mt = 0; mt < 4; mt++) {
#pragma unroll
        for (int rh = 0; rh < 2; rh++) {
            int m = m0 + warp_m * 64 + mt * 16 + (lane >> 2) + rh * 8;
            size_t base = (size_t)m * 1024 + hc0;
            float2 cold = *reinterpret_cast<const float2*>(cprev + base);

            float hn[2], cn[2];
#pragma unroll
            for (int e = 0; e < 2; e++) {
                int rr = rh * 2 + e;
                float gi = acc[mt][0][rr] + bsum[0][e];
                float gf = acc[mt][1][rr] + bsum[1][e];
                float go = acc[mt][2][rr] + bsum[2][e];
                float gc = acc[mt][3][rr] + bsum[3][e];
                float iv = sigmoidf_(gi);
                float fv = sigmoidf_(gf);
                float ov = sigmoidf_(go);
                float ch = tanhf_(gc);
                float cold_e = (e == 0) ? cold.x : cold.y;
                float cv = fv * cold_e + iv * ch;
                cn[e] = cv;
                hn[e] = ov * tanhf_(cv);
            }

            float2 hv = make_float2(hn[0], hn[1]);
            *reinterpret_cast<float2*>(o1 + base) = hv;
            if (o2) *reinterpret_cast<float2*>(o2 + base) = hv;
            if (oc) *reinterpret_cast<float2*>(oc + base) = make_float2(cn[0], cn[1]);
        }
    }
}

extern "C" void kernel_launch(void* const* d_in, const int* in_sizes, int n_in,
                              void* d_out, int out_size) {
    const float* x  = (const float*)d_in[0];
    const float* h  = (const float*)d_in[1];
    const float* c  = (const float*)d_in[2];
    const float* W  = (const float*)d_in[3];
    const float* bW = (const float*)d_in[4];
    const float* U  = (const float*)d_in[5];
    const float* bU = (const float*)d_in[6];
    float* out = (float*)d_out;

    const long long BH = 8192LL * 1024LL;
    float* o1 = out;
    float* o2 = nullptr;
    float* oc = nullptr;
    if ((long long)out_size >= 3 * BH) {          // (h_new, h_new, c_new)
        o2 = out + BH;
        oc = out + 2 * BH;
    } else if ((long long)out_size >= 2 * BH) {   // (h_new, c_new)
        oc = out + BH;
    }

    cvt_f32_to_f16_kernel<<<4096, 256>>>(x, h, W, U);

    cudaFuncSetAttribute(xlstm_f16_mma_kernel,
                         cudaFuncAttributeMaxDynamicSharedMemorySize, SMEM_TOTAL);
    xlstm_f16_mma_kernel<<<2048, NTHREADS, SMEM_TOTAL>>>(c, bW, bU, o1, o2, oc);
}

// round 12
// speedup vs baseline: 1.3136x; 1.0134x over previous
#include <cuda_runtime.h>
#include <cuda_fp16.h>
#include <cstdint>

// ---------------------------------------------------------------------------
// xLSTM cell, fused, portable sm_103 path (no "a" features):
//   pass 1: convert x,h,W,U fp32 -> fp16 scratch (static __device__ buffers)
//   pass 2: G[8192,4096] = [x|h] @ [W|U]^T via mma.m16n8k16.f16, fp32 accum,
//           gating epilogue fused.
//
// R12 = R11 (best, 363.3us) + two changes:
//   (1) warp_m-rotated step order: warp_m=1 processes k16 steps 2,3,0,1 so
//       the two same-CTA warps on an SMSP are never in their LDSM window
//       simultaneously (R11 analysis: ~450 bubble cyc/chunk from lockstep
//       load windows; accumulation commutes so result is fp-reorder only).
//   (2) segmented convert kernel: contiguous 1024-float4 blocks, uniform
//       tensor select per block (28 -> ~19us, DRAM-bound floor).
// Shape unchanged: two 256-thread CTAs/SM, CTA 128m x (4g x 32hc), warp
// 64x32, acc 64, 3-stage 32KB/stage, grid 2048 = 64m x 32h.
// ---------------------------------------------------------------------------

#define NTHREADS 256
#define STAGES 3
#define A_TILE_BYTES 16384            // 128 rows x 128B (64 fp16)
#define B_TILE_BYTES 16384            // 128 rows (4g x 32hc) x 128B
#define STAGE_BYTES  (A_TILE_BYTES + B_TILE_BYTES)   // 32768
#define SMEM_TOTAL   (STAGES * STAGE_BYTES)          // 98304

#define N_X 8388608                   // 8192*1024
#define N_W 4194304                   // 4*1024*1024

__device__ __align__(16) __half g_x16[N_X];
__device__ __align__(16) __half g_h16[N_X];
__device__ __align__(16) __half g_W16[N_W];
__device__ __align__(16) __half g_U16[N_W];

#define SWZ(o) ((o) ^ (((o) >> 3) & 0x70))

static __device__ __forceinline__ uint32_t smem_u32(const void* p) {
    uint32_t a;
    asm("{ .reg .u64 t; cvta.to.shared.u64 t, %1; cvt.u32.u64 %0, t; }"
        : "=r"(a) : "l"(p));
    return a;
}

#define CP_ASYNC16(dst, src) \
    asm volatile("cp.async.cg.shared.global [%0], [%1], 16;" :: "r"(dst), "l"(src) : "memory")
#define CP_COMMIT() asm volatile("cp.async.commit_group;" ::: "memory")
#define CP_WAIT1()  asm volatile("cp.async.wait_group 1;" ::: "memory")

#define LDMATRIX_X4(r0, r1, r2, r3, addr) \
    asm volatile("ldmatrix.sync.aligned.m8n8.x4.shared.b16 {%0,%1,%2,%3}, [%4];" \
                 : "=r"(r0), "=r"(r1), "=r"(r2), "=r"(r3) : "r"(addr))

#define MMA_F16(d, a, b0, b1) \
    asm volatile("mma.sync.aligned.m16n8k16.row.col.f32.f16.f16.f32 " \
                 "{%0,%1,%2,%3}, {%4,%5,%6,%7}, {%8,%9}, {%0,%1,%2,%3};" \
                 : "+f"((d)[0]), "+f"((d)[1]), "+f"((d)[2]), "+f"((d)[3]) \
                 : "r"((a)[0]), "r"((a)[1]), "r"((a)[2]), "r"((a)[3]), \
                   "r"(b0), "r"(b1))

static __device__ __forceinline__ float sigmoidf_(float v) {
    return 1.0f / (1.0f + __expf(-v));
}
static __device__ __forceinline__ float tanhf_(float v) {
    return 1.0f - 2.0f / (__expf(2.0f * v) + 1.0f);
}

// ---------------- pass 1: fp32 -> fp16 conversion (segmented) --------------
// float4 slots: x [0,2M), h [2M,4M), W [4M,5M), U [5M,6M). Block b covers
// contiguous slots [b*1024, (b+1)*1024); tensor select is block-uniform.
#define CVT_BLOCKS 6144
__global__ void __launch_bounds__(256) cvt_f32_to_f16_kernel(
    const float* __restrict__ x, const float* __restrict__ h,
    const float* __restrict__ W, const float* __restrict__ U)
{
    const long long n4x = N_X / 4;            // 2097152
    const long long n4w = N_W / 4;            // 1048576
    long long base = (long long)blockIdx.x * 1024;
    const float* s;
    __half* d;
    if (base < n4x)                       { s = x; d = g_x16; }
    else if (base < 2 * n4x)              { s = h; d = g_h16; base -= n4x; }
    else if (base < 2 * n4x + n4w)        { s = W; d = g_W16; base -= 2 * n4x; }
    else                                  { s = U; d = g_U16; base -= 2 * n4x + n4w; }
#pragma unroll
    for (int r = 0; r < 4; r++) {
        long long j = base + threadIdx.x + r * 256;
        float4 v = reinterpret_cast<const float4*>(s)[j];
        __half2 lo = __floats2half2_rn(v.x, v.y);
        __half2 hi = __floats2half2_rn(v.z, v.w);
        uint2 u;
        u.x = *reinterpret_cast<uint32_t*>(&lo);
        u.y = *reinterpret_cast<uint32_t*>(&hi);
        reinterpret_cast<uint2*>(d)[j] = u;
    }
}

// Load one BK=64 chunk (A 128x64 fp16 + B [4g x 32hc] x 64 fp16) into a stage.
static __device__ __forceinline__ void load_chunk64(
    int kc, uint32_t stage_sm,
    const uint32_t* dst, const int* srcA, const int* srcB)
{
    const __half* ap = (kc < 16) ? g_x16 : g_h16;
    const __half* bp = (kc < 16) ? g_W16 : g_U16;
    int k0 = (kc & 15) << 6;
    uint32_t sB = stage_sm + A_TILE_BYTES;
#pragma unroll
    for (int j = 0; j < 4; j++) CP_ASYNC16(stage_sm + dst[j], ap + srcA[j] + k0);
#pragma unroll
    for (int j = 0; j < 4; j++) CP_ASYNC16(sB + dst[j], bp + srcB[j] + k0);
}

// One BK=64 chunk. Steps are indexed through per-warp ROTATED selectors
// (aSelR/bSelR), so warp_m=0 runs k16 steps 0,1,2,3 and warp_m=1 runs
// 2,3,0,1 -- same accumulation, de-phased smem-load windows.
#define CHUNK_BODY(kc_, CUR_) do {                                           \
    CP_WAIT1();                                                              \
    __syncthreads();                                                         \
    const uint32_t sA_ = sbase + (uint32_t)((CUR_) * STAGE_BYTES);           \
    const uint32_t sB_ = sA_ + A_TILE_BYTES;                                 \
    uint32_t bfr[4][4];                                                      \
    _Pragma("unroll")                                                        \
    for (int g = 0; g < 4; g++)                                              \
        LDMATRIX_X4(bfr[g][0], bfr[g][1], bfr[g][2], bfr[g][3],              \
                    sB_ + bOff[g] + bSelR[0]);                               \
    if ((kc_) + 2 < 32)                                                      \
        load_chunk64((kc_) + 2,                                              \
                     sbase + (uint32_t)((((CUR_) + 2) % 3) * STAGE_BYTES),   \
                     dst, srcA, srcB);                                       \
    CP_COMMIT();                                                             \
    _Pragma("unroll")                                                        \
    for (int kh = 0; kh < 2; kh++) {                                         \
        if (kh == 1) {                                                       \
            _Pragma("unroll")                                                \
            for (int g = 0; g < 4; g++)                                      \
                LDMATRIX_X4(bfr[g][0], bfr[g][1], bfr[g][2], bfr[g][3],      \
                            sB_ + bOff[g] + bSelR[1]);                       \
        }                                                                    \
        _Pragma("unroll")                                                    \
        for (int t = 0; t < 2; t++) {                                        \
            const uint32_t aCh = aSelR[kh * 2 + t];                          \
            const int bs = t << 1;                                           \
            uint32_t afr[4][4];                                              \
            _Pragma("unroll")                                                \
            for (int mt = 0; mt < 4; mt++)                                   \
                LDMATRIX_X4(afr[mt][0], afr[mt][1], afr[mt][2], afr[mt][3],  \
                            sA_ + aOff[mt] + aCh);                           \
            _Pragma("unroll")                                                \
            for (int mt = 0; mt < 4; mt++)                                   \
                _Pragma("unroll")                                            \
                for (int g = 0; g < 4; g++)                                  \
                    MMA_F16(acc[mt][g], afr[mt], bfr[g][bs], bfr[g][bs + 1]);\
        }                                                                    \
    }                                                                        \
} while (0)

__global__ void __launch_bounds__(NTHREADS, 2) xlstm_f16_mma_kernel(
    const float* __restrict__ cprev,
    const float* __restrict__ bW, const float* __restrict__ bU,
    float* __restrict__ o1, float* __restrict__ o2, float* __restrict__ oc)
{
    extern __shared__ char smem[];
    const uint32_t sbase = smem_u32(smem);

    const int tid  = threadIdx.x;
    const int lane = tid & 31;
    const int warp = tid >> 5;
    const int warp_m = warp >> 2;      // 0..1 : 64 m-rows each
    const int warp_n = warp & 3;       // 0..3 : 8 h-cols each (x4 gates)

    const int bid = blockIdx.x;
    const int m0 = (bid >> 5) << 7;    // 64 m-tiles of 128
    const int h0 = (bid & 31) << 5;    // 32 h-tiles of 32

    // ---- cp.async per-thread offsets (slot j: row r = slot/8, 16B chunk cq) ----
    uint32_t dst[4];
    int srcA[4], srcB[4];
#pragma unroll
    for (int j = 0; j < 4; j++) {
        int slot = tid + j * NTHREADS;       // 0..1023
        int r = slot >> 3, cq = slot & 7;
        dst[j] = SWZ((uint32_t)(r * 128 + cq * 16));
        srcA[j] = (m0 + r) * 1024 + cq * 8;
        int g = r >> 5, hc = r & 31;         // B rows: gate-major [4][32]
        srcB[j] = g * 1048576 + (h0 + hc) * 1024 + cq * 8;
    }

    // ---- ldmatrix per-thread address components ----
    const uint32_t xorv = (uint32_t)(lane & 7) << 4;
    uint32_t aOff[4];
#pragma unroll
    for (int mt = 0; mt < 4; mt++)
        aOff[mt] = (uint32_t)(warp_m * 64 + mt * 16 + (lane & 15)) * 128u;
    // base selectors for the 4 k16 steps / 2 k32 halves
    uint32_t aSel[4];
#pragma unroll
    for (int s = 0; s < 4; s++)
        aSel[s] = ((uint32_t)(s * 32) + ((uint32_t)(lane >> 4) << 4)) ^ xorv;
    uint32_t bOff[4];
#pragma unroll
    for (int g = 0; g < 4; g++)
        bOff[g] = (uint32_t)(g * 32 + warp_n * 8 + (lane & 7)) * 128u;
    uint32_t bSel[2];
#pragma unroll
    for (int kh = 0; kh < 2; kh++)
        bSel[kh] = ((uint32_t)(kh * 64) + ((uint32_t)(lane >> 3) << 4)) ^ xorv;

    // warp_m-rotated selectors: warp_m=1 visits steps 2,3,0,1 (kh order 1,0)
    uint32_t aSelR[4], bSelR[2];
#pragma unroll
    for (int s = 0; s < 4; s++) aSelR[s] = aSel[s ^ (warp_m << 1)];
    bSelR[0] = bSel[warp_m];
    bSelR[1] = bSel[warp_m ^ 1];

    float acc[4][4][4];   // [mt][gate][frag]
#pragma unroll
    for (int mt = 0; mt < 4; mt++)
#pragma unroll
        for (int g = 0; g < 4; g++)
#pragma unroll
            for (int r = 0; r < 4; r++) acc[mt][g][r] = 0.0f;

    // ---- prologue: chunks 0,1 into stages 0,1 ----
    load_chunk64(0, sbase, dst, srcA, srcB);
    CP_COMMIT();
    load_chunk64(1, sbase + STAGE_BYTES, dst, srcA, srcB);
    CP_COMMIT();

    // ---- mainloop: 32 BK=64 chunks, stage = chunk % 3 (compile-time) ----
#pragma unroll 1
    for (int kc = 0; kc < 32; kc += 3) {
        CHUNK_BODY(kc, 0);
        CHUNK_BODY(kc + 1, 1);
        if (kc + 2 < 32) CHUNK_BODY(kc + 2, 2);
    }

    // ---- epilogue: thread-local (all 4 gates of each (m,h) in this thread) ----
    const int hc0 = h0 + warp_n * 8 + 2 * (lane & 3);

    float bsum[4][2];
#pragma unroll
    for (int g = 0; g < 4; g++)
#pragma unroll
        for (int e = 0; e < 2; e++)
            bsum[g][e] = bW[g * 1024 + hc0 + e] + bU[g * 1024 + hc0 + e];

#pragma unroll
    for (int mt = 0; mt < 4; mt++) {
#pragma unroll
        for (int rh = 0; rh < 2; rh++) {
            int m = m0 + warp_m * 64 + mt * 16 + (lane >> 2) + rh * 8;
            size_t base = (size_t)m * 1024 + hc0;
            float2 cold = *reinterpret_cast<const float2*>(cprev + base);

            float hn[2], cn[2];
#pragma unroll
            for (int e = 0; e < 2; e++) {
                int rr = rh * 2 + e;
                float gi = acc[mt][0][rr] + bsum[0][e];
                float gf = acc[mt][1][rr] + bsum[1][e];
                float go = acc[mt][2][rr] + bsum[2][e];
                float gc = acc[mt][3][rr] + bsum[3][e];
                float iv = sigmoidf_(gi);
                float fv = sigmoidf_(gf);
                float ov = sigmoidf_(go);
                float ch = tanhf_(gc);
                float cold_e = (e == 0) ? cold.x : cold.y;
                float cv = fv * cold_e + iv * ch;
                cn[e] = cv;
                hn[e] = ov * tanhf_(cv);
            }

            float2 hv = make_float2(hn[0], hn[1]);
            *reinterpret_cast<float2*>(o1 + base) = hv;
            if (o2) *reinterpret_cast<float2*>(o2 + base) = hv;
            if (oc) *reinterpret_cast<float2*>(oc + base) = make_float2(cn[0], cn[1]);
        }
    }
}

extern "C" void kernel_launch(void* const* d_in, const int* in_sizes, int n_in,
                              void* d_out, int out_size) {
    const float* x  = (const float*)d_in[0];
    const float* h  = (const float*)d_in[1];
    const float* c  = (const float*)d_in[2];
    const float* W  = (const float*)d_in[3];
    const float* bW = (const float*)d_in[4];
    const float* U  = (const float*)d_in[5];
    const float* bU = (const float*)d_in[6];
    float* out = (float*)d_out;

    const long long BH = 8192LL * 1024LL;
    float* o1 = out;
    float* o2 = nullptr;
    float* oc = nullptr;
    if ((long long)out_size >= 3 * BH) {          // (h_new, h_new, c_new)
        o2 = out + BH;
        oc = out + 2 * BH;
    } else if ((long long)out_size >= 2 * BH) {   // (h_new, c_new)
        oc = out + BH;
    }

    cvt_f32_to_f16_kernel<<<CVT_BLOCKS, 256>>>(x, h, W, U);

    cudaFuncSetAttribute(xlstm_f16_mma_kernel,
                         cudaFuncAttributeMaxDynamicSharedMemorySize, SMEM_TOTAL);
    xlstm_f16_mma_kernel<<<2048, NTHREADS, SMEM_TOTAL>>>(c, bW, bU, o1, o2, oc);
}